// round 7
// baseline (speedup 1.0000x reference)
#include <cuda_runtime.h>
#include <cstdint>

#define D_MODEL 1024
#define D_STATE 16
#define BATCH   4
#define SEQLEN  4096
#define NROWS   (BATCH*SEQLEN)      // 16384
#define CHUNK2  32
#define NCHUNK2 (SEQLEN/CHUNK2)     // 128
#define ESPLIT  8
#define EB      (D_MODEL/ESPLIT)    // 128 e's per block in K1

// ---------------- device scratch (no allocations allowed) ----------------
__device__ float g_bxp  [ESPLIT][NROWS * D_STATE]; // 8 MB partials
__device__ float g_bx   [NROWS * D_STATE];         // 1 MB
__device__ float g_decay[NROWS * D_STATE];         // 1 MB
__device__ float g_ca   [BATCH * NCHUNK2 * D_STATE];
__device__ float g_cv   [BATCH * NCHUNK2 * D_STATE];
__device__ float g_h0   [BATCH * NCHUNK2 * D_STATE];

// ---------------- f32x2 helpers ----------------
static __device__ __forceinline__ unsigned long long pack2(float lo, float hi) {
    unsigned long long r;
    asm("mov.b64 %0, {%1, %2};" : "=l"(r) : "f"(lo), "f"(hi));
    return r;
}
static __device__ __forceinline__ void unpack2(unsigned long long v, float& lo, float& hi) {
    asm("mov.b64 {%0, %1}, %2;" : "=f"(lo), "=f"(hi) : "l"(v));
}
static __device__ __forceinline__ unsigned long long fma2(unsigned long long a, unsigned long long b, unsigned long long c) {
    unsigned long long d;
    asm("fma.rn.f32x2 %0, %1, %2, %3;" : "=l"(d) : "l"(a), "l"(b), "l"(c));
    return d;
}
static __device__ __forceinline__ unsigned long long mul2(unsigned long long a, unsigned long long b) {
    unsigned long long d;
    asm("mul.rn.f32x2 %0, %1, %2;" : "=l"(d) : "l"(a), "l"(b));
    return d;
}

// =======================================================================
// K1: partial Bx over e-slice. grid (64, 8), block 256 (8 warps).
// =======================================================================
__global__ void __launch_bounds__(256, 4) k_bx(const float* __restrict__ x,
                                               const float* __restrict__ Bin)
{
    __shared__ float sB[EB * D_STATE];   // 8 KB
    __shared__ float xt[8][32 * 32];     // 32 KB

    const int tid  = threadIdx.x;
    const int w    = tid >> 5;
    const int lane = tid & 31;
    const int eBase   = blockIdx.y * EB;
    const int rowBase = blockIdx.x * 256 + w * 32;

    {
        const float4* B4 = (const float4*)(Bin + eBase * D_STATE);
        float4* sB4 = (float4*)sB;
        #pragma unroll
        for (int i = tid; i < EB * 4; i += 256) sB4[i] = B4[i];
    }
    __syncthreads();

    unsigned long long acc[8];
    #pragma unroll
    for (int j = 0; j < 8; j++) acc[j] = 0ull;

    const ulonglong2* sBu = (const ulonglong2*)sB;
    const float4* x4 = (const float4*)x;
    float* xtw = xt[w];

    const int rlo = lane >> 3;
    const int c4  = (lane & 7) * 4;

    #pragma unroll
    for (int t = 0; t < 4; t++) {
        const int eb4 = (eBase >> 2) + t * 8;
        __syncwarp();
        #pragma unroll
        for (int j = 0; j < 8; j++) {
            int rr = j * 4 + rlo;
            float4 xv = __ldg(x4 + (size_t)(rowBase + rr) * 256 + eb4 + (lane & 7));
            xtw[(c4 + 0) * 32 + (rr ^ (c4 + 0))] = xv.x;
            xtw[(c4 + 1) * 32 + (rr ^ (c4 + 1))] = xv.y;
            xtw[(c4 + 2) * 32 + (rr ^ (c4 + 2))] = xv.z;
            xtw[(c4 + 3) * 32 + (rr ^ (c4 + 3))] = xv.w;
        }
        __syncwarp();
        #pragma unroll
        for (int el = 0; el < 32; el++) {
            float xv = xtw[el * 32 + (lane ^ el)];
            unsigned long long xx = pack2(xv, xv);
            int e = t * 32 + el;
            ulonglong2 q0 = sBu[e * 4 + 0];
            ulonglong2 q1 = sBu[e * 4 + 1];
            ulonglong2 q2 = sBu[e * 4 + 2];
            ulonglong2 q3 = sBu[e * 4 + 3];
            acc[0] = fma2(q0.x, xx, acc[0]);
            acc[1] = fma2(q0.y, xx, acc[1]);
            acc[2] = fma2(q1.x, xx, acc[2]);
            acc[3] = fma2(q1.y, xx, acc[3]);
            acc[4] = fma2(q2.x, xx, acc[4]);
            acc[5] = fma2(q2.y, xx, acc[5]);
            acc[6] = fma2(q3.x, xx, acc[6]);
            acc[7] = fma2(q3.y, xx, acc[7]);
        }
    }

    const int row = rowBase + lane;
    float v[16];
    #pragma unroll
    for (int j = 0; j < 8; j++) unpack2(acc[j], v[2 * j], v[2 * j + 1]);
    float4* gp = (float4*)(&g_bxp[blockIdx.y][row * D_STATE]);
    #pragma unroll
    for (int q = 0; q < 4; q++)
        gp[q] = make_float4(v[4 * q], v[4 * q + 1], v[4 * q + 2], v[4 * q + 3]);
}

// =======================================================================
// K1.5: sum partials, softplus, decay.
// =======================================================================
__global__ void __launch_bounds__(256) k_combine(const float* __restrict__ A)
{
    const int idx = blockIdx.x * 256 + threadIdx.x;   // float4 index
    float4 s = make_float4(0.f, 0.f, 0.f, 0.f);
    #pragma unroll
    for (int p = 0; p < ESPLIT; p++) {
        float4 v = __ldg((const float4*)g_bxp[p] + idx);
        s.x += v.x; s.y += v.y; s.z += v.z; s.w += v.w;
    }
    const int q = (idx & 3) * 4;
    float4 d;
    {
        float a0 = -expf(__ldg(A + q + 0));
        float a1 = -expf(__ldg(A + q + 1));
        float a2 = -expf(__ldg(A + q + 2));
        float a3 = -expf(__ldg(A + q + 3));
        float sp;
        sp = fmaxf(s.x, 0.f) + log1pf(expf(-fabsf(s.x))); d.x = expf(sp * a0);
        sp = fmaxf(s.y, 0.f) + log1pf(expf(-fabsf(s.y))); d.y = expf(sp * a1);
        sp = fmaxf(s.z, 0.f) + log1pf(expf(-fabsf(s.z))); d.z = expf(sp * a2);
        sp = fmaxf(s.w, 0.f) + log1pf(expf(-fabsf(s.w))); d.w = expf(sp * a3);
    }
    ((float4*)g_bx)[idx]    = s;
    ((float4*)g_decay)[idx] = d;
}

// =======================================================================
// K2a: chunk aggregates, 32 blocks x 256 threads (16 chunks per block).
// =======================================================================
__global__ void __launch_bounds__(256) k_agg()
{
    const int b  = blockIdx.x >> 3;
    const int cg = blockIdx.x & 7;
    const int cl = threadIdx.x >> 4;
    const int s  = threadIdx.x & 15;
    const int cc = cg * 16 + cl;

    int base = (b * SEQLEN + cc * CHUNK2) * D_STATE + s;
    float a = 1.0f, v = 0.0f;
    #pragma unroll 8
    for (int t = 0; t < CHUNK2; t++) {
        float d   = g_decay[base + t * D_STATE];
        float bxv = g_bx   [base + t * D_STATE];
        v = fmaf(v, d, bxv);
        a *= d;
    }
    g_ca[(b * NCHUNK2 + cc) * 16 + s] = a;
    g_cv[(b * NCHUNK2 + cc) * 16 + s] = v;
}

// =======================================================================
// K2b: serial boundary scan, 1 block x 64 threads (4 batches x 16 states).
// =======================================================================
__global__ void __launch_bounds__(64) k_scan2()
{
    const int tid = threadIdx.x;
    const int b   = tid >> 4;
    const int s   = tid & 15;
    const int base = b * NCHUNK2 * 16 + s;
    float h = 0.0f;
    #pragma unroll 4
    for (int cc = 0; cc < NCHUNK2; cc++) {
        g_h0[base + cc * 16] = h;
        h = fmaf(g_ca[base + cc * 16], h, g_cv[base + cc * 16]);
    }
}

// =======================================================================
// K3: per-chunk local scan + y = h @ C + x*D
// grid = BATCH*NCHUNK2*2 = 1024 blocks x 256 threads; 2 cols/thread.
// =======================================================================
__global__ void __launch_bounds__(256, 4) k_out(const float* __restrict__ x,
                                                const float* __restrict__ C,
                                                const float* __restrict__ D,
                                                float* __restrict__ y)
{
    __shared__ __align__(16) float hh[CHUNK2][16];
    const int idx  = blockIdx.x;
    const int half = idx & 1;
    const int c    = (idx >> 1) & 127;
    const int b    = idx >> 8;
    const int tid  = threadIdx.x;
    const int row0 = b * SEQLEN + c * CHUNK2;
    const int col0 = half * 512 + tid * 2;

    // C tile: 16 states x 2 cols -> 16 f32x2 regs
    unsigned long long ca[16];
    #pragma unroll
    for (int s = 0; s < 16; s++) {
        float2 cv = __ldg((const float2*)(C + s * D_MODEL + col0));
        ca[s] = pack2(cv.x, cv.y);
    }
    float2 dv = __ldg((const float2*)(D + col0));
    bool anyD = (dv.x != 0.0f) || (dv.y != 0.0f);
    unsigned long long d01 = pack2(dv.x, dv.y);

    // local 32-step scan by lanes 0..15
    if (tid < 16) {
        float h = g_h0[(b * NCHUNK2 + c) * 16 + tid];
        int base = row0 * D_STATE + tid;
        float dA[8], vA[8], dB[8], vB[8];
        #pragma unroll
        for (int k = 0; k < 8; k++) {
            dA[k] = g_decay[base + k * 16];
            vA[k] = g_bx   [base + k * 16];
        }
        #pragma unroll
        for (int g = 0; g < 4; g++) {
            if (g < 3) {
                #pragma unroll
                for (int k = 0; k < 8; k++) {
                    dB[k] = g_decay[base + ((g + 1) * 8 + k) * 16];
                    vB[k] = g_bx   [base + ((g + 1) * 8 + k) * 16];
                }
            }
            #pragma unroll
            for (int k = 0; k < 8; k++) {
                h = fmaf(h, dA[k], vA[k]);
                hh[g * 8 + k][tid] = h;
            }
            #pragma unroll
            for (int k = 0; k < 8; k++) { dA[k] = dB[k]; vA[k] = vB[k]; }
        }
    }
    __syncthreads();

    #pragma unroll 2
    for (int t = 0; t < CHUNK2; t++) {
        unsigned long long y01;
        if (anyD) {
            float2 xv = __ldg((const float2*)(x + (size_t)(row0 + t) * D_MODEL + col0));
            y01 = mul2(pack2(xv.x, xv.y), d01);
        } else {
            y01 = 0ull;
        }
        const float4* hf = (const float4*)hh[t];  // broadcast
        float4 h0 = hf[0], h1 = hf[1], h2 = hf[2], h3 = hf[3];

        #define SSTEP(hv, s) { unsigned long long hs = pack2((hv), (hv)); \
                               y01 = fma2(hs, ca[s], y01); }
        SSTEP(h0.x, 0)  SSTEP(h0.y, 1)  SSTEP(h0.z, 2)  SSTEP(h0.w, 3)
        SSTEP(h1.x, 4)  SSTEP(h1.y, 5)  SSTEP(h1.z, 6)  SSTEP(h1.w, 7)
        SSTEP(h2.x, 8)  SSTEP(h2.y, 9)  SSTEP(h2.z,10)  SSTEP(h2.w,11)
        SSTEP(h3.x,12)  SSTEP(h3.y,13)  SSTEP(h3.z,14)  SSTEP(h3.w,15)
        #undef SSTEP

        float2 out;
        unpack2(y01, out.x, out.y);
        *(float2*)(y + (size_t)(row0 + t) * D_MODEL + col0) = out;
    }
}

// =======================================================================
extern "C" void kernel_launch(void* const* d_in, const int* in_sizes, int n_in,
                              void* d_out, int out_size)
{
    const float* x   = (const float*)d_in[0];
    const float* A   = (const float*)d_in[1];
    const float* Bin = (const float*)d_in[2];
    const float* C   = (const float*)d_in[3];
    const float* D   = (const float*)d_in[4];
    float* y = (float*)d_out;

    dim3 g1(NROWS / 256, ESPLIT);
    k_bx<<<g1, 256>>>(x, Bin);
    k_combine<<<(NROWS * 4) / 256, 256>>>(A);
    k_agg<<<BATCH * 8, 256>>>();
    k_scan2<<<1, 64>>>();
    k_out<<<BATCH * NCHUNK2 * 2, 256>>>(x, C, D, y);
}

// round 10
// speedup vs baseline: 1.5139x; 1.5139x over previous
#include <cuda_runtime.h>
#include <cstdint>

#define D_MODEL 1024
#define D_STATE 16
#define BATCH   4
#define SEQLEN  4096
#define NROWS   (BATCH*SEQLEN)      // 16384
#define CHUNK2  32
#define NCHUNK2 (SEQLEN/CHUNK2)     // 128
#define ESPLIT  8
#define EB      (D_MODEL/ESPLIT)    // 128 e's per block in K1

// ---------------- device scratch (no allocations allowed) ----------------
__device__ float g_bxp  [ESPLIT][NROWS * D_STATE]; // 8 MB partials
__device__ float g_bx   [NROWS * D_STATE];         // 1 MB
__device__ float g_decay[NROWS * D_STATE];         // 1 MB
__device__ float g_ca   [BATCH * NCHUNK2 * D_STATE];
__device__ float g_cv   [BATCH * NCHUNK2 * D_STATE];
__device__ float g_h0   [BATCH * NCHUNK2 * D_STATE];

// ---------------- f32x2 helpers ----------------
static __device__ __forceinline__ unsigned long long pack2(float lo, float hi) {
    unsigned long long r;
    asm("mov.b64 %0, {%1, %2};" : "=l"(r) : "f"(lo), "f"(hi));
    return r;
}
static __device__ __forceinline__ void unpack2(unsigned long long v, float& lo, float& hi) {
    asm("mov.b64 {%0, %1}, %2;" : "=f"(lo), "=f"(hi) : "l"(v));
}
static __device__ __forceinline__ unsigned long long fma2(unsigned long long a, unsigned long long b, unsigned long long c) {
    unsigned long long d;
    asm("fma.rn.f32x2 %0, %1, %2, %3;" : "=l"(d) : "l"(a), "l"(b), "l"(c));
    return d;
}
static __device__ __forceinline__ unsigned long long mul2(unsigned long long a, unsigned long long b) {
    unsigned long long d;
    asm("mul.rn.f32x2 %0, %1, %2;" : "=l"(d) : "l"(a), "l"(b));
    return d;
}

// =======================================================================
// K1: partial Bx over e-slice. grid (64, 8), block 256 (8 warps).
// =======================================================================
__global__ void __launch_bounds__(256, 4) k_bx(const float* __restrict__ x,
                                               const float* __restrict__ Bin)
{
    __shared__ float sB[EB * D_STATE];   // 8 KB
    __shared__ float xt[8][32 * 32];     // 32 KB

    const int tid  = threadIdx.x;
    const int w    = tid >> 5;
    const int lane = tid & 31;
    const int eBase   = blockIdx.y * EB;
    const int rowBase = blockIdx.x * 256 + w * 32;

    {
        const float4* B4 = (const float4*)(Bin + eBase * D_STATE);
        float4* sB4 = (float4*)sB;
        #pragma unroll
        for (int i = tid; i < EB * 4; i += 256) sB4[i] = B4[i];
    }
    __syncthreads();

    unsigned long long acc[8];
    #pragma unroll
    for (int j = 0; j < 8; j++) acc[j] = 0ull;

    const ulonglong2* sBu = (const ulonglong2*)sB;
    const float4* x4 = (const float4*)x;
    float* xtw = xt[w];

    const int rlo = lane >> 3;
    const int c4  = (lane & 7) * 4;

    #pragma unroll
    for (int t = 0; t < 4; t++) {
        const int eb4 = (eBase >> 2) + t * 8;
        __syncwarp();
        #pragma unroll
        for (int j = 0; j < 8; j++) {
            int rr = j * 4 + rlo;
            float4 xv = __ldg(x4 + (size_t)(rowBase + rr) * 256 + eb4 + (lane & 7));
            xtw[(c4 + 0) * 32 + (rr ^ (c4 + 0))] = xv.x;
            xtw[(c4 + 1) * 32 + (rr ^ (c4 + 1))] = xv.y;
            xtw[(c4 + 2) * 32 + (rr ^ (c4 + 2))] = xv.z;
            xtw[(c4 + 3) * 32 + (rr ^ (c4 + 3))] = xv.w;
        }
        __syncwarp();
        #pragma unroll
        for (int el = 0; el < 32; el++) {
            float xv = xtw[el * 32 + (lane ^ el)];
            unsigned long long xx = pack2(xv, xv);
            int e = t * 32 + el;
            ulonglong2 q0 = sBu[e * 4 + 0];
            ulonglong2 q1 = sBu[e * 4 + 1];
            ulonglong2 q2 = sBu[e * 4 + 2];
            ulonglong2 q3 = sBu[e * 4 + 3];
            acc[0] = fma2(q0.x, xx, acc[0]);
            acc[1] = fma2(q0.y, xx, acc[1]);
            acc[2] = fma2(q1.x, xx, acc[2]);
            acc[3] = fma2(q1.y, xx, acc[3]);
            acc[4] = fma2(q2.x, xx, acc[4]);
            acc[5] = fma2(q2.y, xx, acc[5]);
            acc[6] = fma2(q3.x, xx, acc[6]);
            acc[7] = fma2(q3.y, xx, acc[7]);
        }
    }

    const int row = rowBase + lane;
    float v[16];
    #pragma unroll
    for (int j = 0; j < 8; j++) unpack2(acc[j], v[2 * j], v[2 * j + 1]);
    float4* gp = (float4*)(&g_bxp[blockIdx.y][row * D_STATE]);
    #pragma unroll
    for (int q = 0; q < 4; q++)
        gp[q] = make_float4(v[4 * q], v[4 * q + 1], v[4 * q + 2], v[4 * q + 3]);
}

// =======================================================================
// K1.5: sum partials, softplus, decay, AND per-chunk aggregates.
// Block covers 64 consecutive rows = exactly 2 chunks of 32.
// Chunk-1 rows are offset +16 floats in smem so the two 16-lane
// aggregate loops hit disjoint bank sets.
// =======================================================================
__global__ void __launch_bounds__(256) k_combine(const float* __restrict__ A)
{
    __shared__ float sbx[64 * 16 + 16];
    __shared__ float sdc[64 * 16 + 16];

    const int tid = threadIdx.x;
    const int idx = blockIdx.x * 256 + tid;   // float4 index
    float4 s = make_float4(0.f, 0.f, 0.f, 0.f);
    #pragma unroll
    for (int p = 0; p < ESPLIT; p++) {
        float4 v = __ldg((const float4*)g_bxp[p] + idx);
        s.x += v.x; s.y += v.y; s.z += v.z; s.w += v.w;
    }
    const int q = (idx & 3) * 4;
    float4 d;
    {
        float a0 = -expf(__ldg(A + q + 0));
        float a1 = -expf(__ldg(A + q + 1));
        float a2 = -expf(__ldg(A + q + 2));
        float a3 = -expf(__ldg(A + q + 3));
        float sp;
        sp = fmaxf(s.x, 0.f) + log1pf(expf(-fabsf(s.x))); d.x = expf(sp * a0);
        sp = fmaxf(s.y, 0.f) + log1pf(expf(-fabsf(s.y))); d.y = expf(sp * a1);
        sp = fmaxf(s.z, 0.f) + log1pf(expf(-fabsf(s.z))); d.z = expf(sp * a2);
        sp = fmaxf(s.w, 0.f) + log1pf(expf(-fabsf(s.w))); d.w = expf(sp * a3);
    }
    ((float4*)g_bx)[idx]    = s;
    ((float4*)g_decay)[idx] = d;

    // stash in smem for chunk aggregation
    const int rl  = tid >> 2;                       // local row 0..63
    const int off = rl * 16 + ((tid & 3) * 4) + (rl >= 32 ? 16 : 0);
    *(float4*)&sbx[off] = s;
    *(float4*)&sdc[off] = d;
    __syncthreads();

    if (tid < 32) {
        const int cl = tid >> 4;                    // 0..1 chunk within block
        const int st = tid & 15;
        const int base = cl * (32 * 16 + 16) + st;
        float a = 1.0f, v = 0.0f;
        #pragma unroll 8
        for (int t = 0; t < CHUNK2; t++) {
            float dd = sdc[base + t * 16];
            float bb = sbx[base + t * 16];
            v = fmaf(v, dd, bb);
            a *= dd;
        }
        const int r0 = blockIdx.x * 64;             // first global row of block
        const int b  = r0 >> 12;                    // /SEQLEN
        const int cc = ((r0 & (SEQLEN - 1)) >> 5) + cl;
        const int gi = (b * NCHUNK2 + cc) * 16 + st;
        g_ca[gi] = a;
        g_cv[gi] = v;
    }
}

// =======================================================================
// K2b: boundary scan, 1 block per batch. Parallel smem staging (float4),
// then 16-lane serial scan from smem (no global latency in the chain).
// =======================================================================
__global__ void __launch_bounds__(256) k_scan2()
{
    __shared__ float sa[NCHUNK2 * D_STATE];   // 8 KB
    __shared__ float sv[NCHUNK2 * D_STATE];   // 8 KB
    const int b   = blockIdx.x;
    const int tid = threadIdx.x;

    const float4* ga = (const float4*)(g_ca + b * NCHUNK2 * D_STATE);
    const float4* gv = (const float4*)(g_cv + b * NCHUNK2 * D_STATE);
    #pragma unroll
    for (int i = tid; i < (NCHUNK2 * D_STATE) / 4; i += 256) {
        ((float4*)sa)[i] = __ldg(ga + i);
        ((float4*)sv)[i] = __ldg(gv + i);
    }
    __syncthreads();

    if (tid < 16) {
        const int base = b * NCHUNK2 * D_STATE + tid;
        float h = 0.0f;
        #pragma unroll 8
        for (int cc = 0; cc < NCHUNK2; cc++) {
            g_h0[base + cc * D_STATE] = h;
            h = fmaf(sa[cc * D_STATE + tid], h, sv[cc * D_STATE + tid]);
        }
    }
}

// =======================================================================
// K3: per-chunk local scan + y = h @ C + x*D
// grid = BATCH*NCHUNK2*2 = 1024 blocks x 256 threads; 2 cols/thread.
// =======================================================================
__global__ void __launch_bounds__(256, 4) k_out(const float* __restrict__ x,
                                                const float* __restrict__ C,
                                                const float* __restrict__ D,
                                                float* __restrict__ y)
{
    __shared__ __align__(16) float hh[CHUNK2][16];
    const int idx  = blockIdx.x;
    const int half = idx & 1;
    const int c    = (idx >> 1) & 127;
    const int b    = idx >> 8;
    const int tid  = threadIdx.x;
    const int row0 = b * SEQLEN + c * CHUNK2;
    const int col0 = half * 512 + tid * 2;

    // C tile: 16 states x 2 cols -> 16 f32x2 regs
    unsigned long long ca[16];
    #pragma unroll
    for (int s = 0; s < 16; s++) {
        float2 cv = __ldg((const float2*)(C + s * D_MODEL + col0));
        ca[s] = pack2(cv.x, cv.y);
    }
    float2 dv = __ldg((const float2*)(D + col0));
    bool anyD = (dv.x != 0.0f) || (dv.y != 0.0f);
    unsigned long long d01 = pack2(dv.x, dv.y);

    // local 32-step scan by lanes 0..15
    if (tid < 16) {
        float h = g_h0[(b * NCHUNK2 + c) * 16 + tid];
        int base = row0 * D_STATE + tid;
        float dA[8], vA[8], dB[8], vB[8];
        #pragma unroll
        for (int k = 0; k < 8; k++) {
            dA[k] = g_decay[base + k * 16];
            vA[k] = g_bx   [base + k * 16];
        }
        #pragma unroll
        for (int g = 0; g < 4; g++) {
            if (g < 3) {
                #pragma unroll
                for (int k = 0; k < 8; k++) {
                    dB[k] = g_decay[base + ((g + 1) * 8 + k) * 16];
                    vB[k] = g_bx   [base + ((g + 1) * 8 + k) * 16];
                }
            }
            #pragma unroll
            for (int k = 0; k < 8; k++) {
                h = fmaf(h, dA[k], vA[k]);
                hh[g * 8 + k][tid] = h;
            }
            #pragma unroll
            for (int k = 0; k < 8; k++) { dA[k] = dB[k]; vA[k] = vB[k]; }
        }
    }
    __syncthreads();

    #pragma unroll 2
    for (int t = 0; t < CHUNK2; t++) {
        unsigned long long y01;
        if (anyD) {
            float2 xv = __ldg((const float2*)(x + (size_t)(row0 + t) * D_MODEL + col0));
            y01 = mul2(pack2(xv.x, xv.y), d01);
        } else {
            y01 = 0ull;
        }
        const float4* hf = (const float4*)hh[t];  // broadcast
        float4 h0 = hf[0], h1 = hf[1], h2 = hf[2], h3 = hf[3];

        #define SSTEP(hv, s) { unsigned long long hs = pack2((hv), (hv)); \
                               y01 = fma2(hs, ca[s], y01); }
        SSTEP(h0.x, 0)  SSTEP(h0.y, 1)  SSTEP(h0.z, 2)  SSTEP(h0.w, 3)
        SSTEP(h1.x, 4)  SSTEP(h1.y, 5)  SSTEP(h1.z, 6)  SSTEP(h1.w, 7)
        SSTEP(h2.x, 8)  SSTEP(h2.y, 9)  SSTEP(h2.z,10)  SSTEP(h2.w,11)
        SSTEP(h3.x,12)  SSTEP(h3.y,13)  SSTEP(h3.z,14)  SSTEP(h3.w,15)
        #undef SSTEP

        float2 out;
        unpack2(y01, out.x, out.y);
        *(float2*)(y + (size_t)(row0 + t) * D_MODEL + col0) = out;
    }
}

// =======================================================================
extern "C" void kernel_launch(void* const* d_in, const int* in_sizes, int n_in,
                              void* d_out, int out_size)
{
    const float* x   = (const float*)d_in[0];
    const float* A   = (const float*)d_in[1];
    const float* Bin = (const float*)d_in[2];
    const float* C   = (const float*)d_in[3];
    const float* D   = (const float*)d_in[4];
    float* y = (float*)d_out;

    dim3 g1(NROWS / 256, ESPLIT);
    k_bx<<<g1, 256>>>(x, Bin);
    k_combine<<<(NROWS * 4) / 256, 256>>>(A);
    k_scan2<<<BATCH, 256>>>();
    k_out<<<BATCH * NCHUNK2 * 2, 256>>>(x, C, D, y);
}